// round 11
// baseline (speedup 1.0000x reference)
#include <cuda_runtime.h>
#include <cstdint>

// Differentiable A* forward, N=4096, Tmax=N/4. Single persistent block, 1024 thr.
// One __syncthreads per iteration. Keys (exp bits) cached in registers, MUFU
// only on relax. Both reduction stages use redux_max + redux_min(index) —
// tie -> lowest index via lane/warp position == index order. Row loaded with
// __ldcg (rows are touched exactly once; skip L1 allocation).

#define NMAX 4096
#define TPB  1024
#define VPT  4          // nodes per thread

__global__ __launch_bounds__(TPB, 1)
void astar_persistent_kernel(const int* __restrict__ start_p,
                             const int* __restrict__ goal_p,
                             const float* __restrict__ h_in,
                             const float* __restrict__ wadj,
                             float* __restrict__ out,
                             int N)
{
    __shared__ float          sm_g[NMAX];
    __shared__ unsigned short sm_par[NMAX];
    __shared__ __align__(16) uint2 sm_warp[2][32];   // (vmax, bestj), x2 parity

    const int tid  = threadIdx.x;
    const int lane = tid & 31;
    const int wid  = tid >> 5;                       // warp order == index order
    const int start = start_p[0];
    const int goal  = goal_p[0];
    const float inv_sqrt_n = 1.0f / sqrtf((float)N); // exactly 1/64 for N=4096
    const int Tmax = N / 4;
    const int j0 = tid * VPT;

    // ---- init: g0 = wadj[start] row (diag zeroed), open = {start} ----
    float    h4[VPT];
    unsigned val[VPT];            // key = bits of expf(-f/64) if open else 0
    unsigned openm = 0, histm = 0;
    {
        float4 hv = reinterpret_cast<const float4*>(h_in)[tid];
        float4 g0 = reinterpret_cast<const float4*>(wadj + (size_t)start * N)[tid];
        h4[0] = hv.x; h4[1] = hv.y; h4[2] = hv.z; h4[3] = hv.w;
        float g4[VPT] = {g0.x, g0.y, g0.z, g0.w};
        #pragma unroll
        for (int k = 0; k < VPT; k++) {
            int j = j0 + k;
            float g = (j == start) ? 0.0f : g4[k];
            sm_g[j]   = g;
            sm_par[j] = (unsigned short)goal;        // parents0 = goal
            val[k] = 0u;
            if (j == start) {
                openm |= 1u << k;
                val[k] = __float_as_uint(expf(-(0.5f * g + 0.5f * h4[k]) * inv_sqrt_n));
            }
        }
    }
    __syncthreads();

    bool done = false;
    int  t_final = 0;

    for (int t = 0; t < Tmax; t++) {
        // ---- lane-local best (ascending strict > ==> lowest k on tie) ----
        unsigned bestv = 0u;
        int      bestj = j0;
        #pragma unroll
        for (int k = 0; k < VPT; k++)
            if (val[k] > bestv) { bestv = val[k]; bestj = j0 + k; }

        // ---- warp stage: max key, then min index among maxima ----
        unsigned vmax = __reduce_max_sync(0xFFFFFFFFu, bestv);
        unsigned jmin = __reduce_min_sync(0xFFFFFFFFu,
                            (bestv == vmax) ? (unsigned)bestj : 0x7FFFFFFFu);
        if (lane == 0) sm_warp[t & 1][wid] = make_uint2(vmax, jmin);

        __syncthreads();   // the ONLY barrier per iteration

        // ---- block combine: lane i <- warp i entry; same dual-redux ----
        uint2 e = sm_warp[t & 1][lane];              // 1 LDS.64, conflict-free
        unsigned gv  = __reduce_max_sync(0xFFFFFFFFu, e.x);
        const int ind = (int)__reduce_min_sync(0xFFFFFFFFu,
                            (e.x == gv) ? e.y : 0x7FFFFFFFu);
        // empty open: all keys 0 -> gv=0, min bestj over warp bases = 0,
        // matching reference argmax-of-zeros fallback.

        // ---- fetch selected row (L2-warm; evict L1 — rows never reused) ----
        const float g_ind = sm_g[ind];    // ind is never relaxed this iteration
        float4 wv = __ldcg(reinterpret_cast<const float4*>(wadj + (size_t)ind * N) + tid);
        float w4a[VPT] = {wv.x, wv.y, wv.z, wv.w};

        t_final = t;
        if (ind == goal) done = true;

        // ---- close ind (open2/hist2) ----
        if ((unsigned)(ind - j0) < VPT) {
            int k = ind - j0;
            openm &= ~(1u << k);
            histm |=  (1u << k);
            val[k] = 0u;
        }
        // ---- relax: idx == neighbor == (w!=0) & free ----
        const unsigned freem = ~(openm | histm);
        #pragma unroll
        for (int k = 0; k < VPT; k++) {
            float w = w4a[k];
            if (w != 0.0f && ((freem >> k) & 1u)) {
                int j = j0 + k;
                float gn = g_ind + w;                // g2 = g[ind] + wadj[ind,j]
                sm_g[j]   = gn;
                sm_par[j] = (unsigned short)ind;
                val[k] = __float_as_uint(expf(-(0.5f * gn + 0.5f * h4[k]) * inv_sqrt_n));
                openm |= 1u << k;                    // open3
            }
        }

        if (done) break;   // uniform branch; state frozen after goal found
    }

    __syncthreads();       // drain final sm_par writes before readout/backtrack

    // ---- outputs: [0,N) hist, [N,2N) path_maps ----
    #pragma unroll
    for (int k = 0; k < VPT; k++) {
        int j = j0 + k;
        out[j]     = ((histm >> k) & 1u) ? 1.0f : 0.0f;
        out[N + j] = 0.0f;
    }
    __syncthreads();

    if (tid == 0) {
        out[N + goal] = 1.0f;                        // path0 = goal one-hot
        int loc = sm_par[goal];
        for (int i = 0; i < t_final; i++) {
            out[N + loc] = 1.0f;
            loc = sm_par[loc];
        }
    }
}

extern "C" void kernel_launch(void* const* d_in, const int* in_sizes, int n_in,
                              void* d_out, int out_size)
{
    const int*   start = (const int*)  d_in[0];
    const int*   goal  = (const int*)  d_in[1];
    const float* h     = (const float*)d_in[2];
    // d_in[3] = nodes (unused), d_in[4] = adj (redundant with wadj != 0)
    const float* wadj  = (const float*)d_in[5];
    float* out = (float*)d_out;
    int N = in_sizes[2];                             // 4096

    astar_persistent_kernel<<<1, TPB>>>(start, goal, h, wadj, out, N);
}

// round 12
// speedup vs baseline: 1.0018x; 1.0018x over previous
#include <cuda_runtime.h>
#include <cstdint>

// Differentiable A* forward, N=4096, Tmax=N/4. Single persistent block, 1024 thr.
// One __syncthreads per iteration. Keys (exp bits) cached in registers, MUFU
// only on relax. Both reduction stages use redux_max + redux_min(index) —
// tie -> lowest index via lane/warp position == index order. Row loaded with
// __ldcg (rows are touched exactly once; skip L1 allocation).

#define NMAX 4096
#define TPB  1024
#define VPT  4          // nodes per thread

__global__ __launch_bounds__(TPB, 1)
void astar_persistent_kernel(const int* __restrict__ start_p,
                             const int* __restrict__ goal_p,
                             const float* __restrict__ h_in,
                             const float* __restrict__ wadj,
                             float* __restrict__ out,
                             int N)
{
    __shared__ float          sm_g[NMAX];
    __shared__ unsigned short sm_par[NMAX];
    __shared__ __align__(16) uint2 sm_warp[2][32];   // (vmax, bestj), x2 parity

    const int tid  = threadIdx.x;
    const int lane = tid & 31;
    const int wid  = tid >> 5;                       // warp order == index order
    const int start = start_p[0];
    const int goal  = goal_p[0];
    const float inv_sqrt_n = 1.0f / sqrtf((float)N); // exactly 1/64 for N=4096
    const int Tmax = N / 4;
    const int j0 = tid * VPT;

    // ---- init: g0 = wadj[start] row (diag zeroed), open = {start} ----
    float    h4[VPT];
    unsigned val[VPT];            // key = bits of expf(-f/64) if open else 0
    unsigned openm = 0, histm = 0;
    {
        float4 hv = reinterpret_cast<const float4*>(h_in)[tid];
        float4 g0 = reinterpret_cast<const float4*>(wadj + (size_t)start * N)[tid];
        h4[0] = hv.x; h4[1] = hv.y; h4[2] = hv.z; h4[3] = hv.w;
        float g4[VPT] = {g0.x, g0.y, g0.z, g0.w};
        #pragma unroll
        for (int k = 0; k < VPT; k++) {
            int j = j0 + k;
            float g = (j == start) ? 0.0f : g4[k];
            sm_g[j]   = g;
            sm_par[j] = (unsigned short)goal;        // parents0 = goal
            val[k] = 0u;
            if (j == start) {
                openm |= 1u << k;
                val[k] = __float_as_uint(expf(-(0.5f * g + 0.5f * h4[k]) * inv_sqrt_n));
            }
        }
    }
    __syncthreads();

    bool done = false;
    int  t_final = 0;

    for (int t = 0; t < Tmax; t++) {
        // ---- lane-local best (ascending strict > ==> lowest k on tie) ----
        unsigned bestv = 0u;
        int      bestj = j0;
        #pragma unroll
        for (int k = 0; k < VPT; k++)
            if (val[k] > bestv) { bestv = val[k]; bestj = j0 + k; }

        // ---- warp stage: max key, then min index among maxima ----
        unsigned vmax = __reduce_max_sync(0xFFFFFFFFu, bestv);
        unsigned jmin = __reduce_min_sync(0xFFFFFFFFu,
                            (bestv == vmax) ? (unsigned)bestj : 0x7FFFFFFFu);
        if (lane == 0) sm_warp[t & 1][wid] = make_uint2(vmax, jmin);

        __syncthreads();   // the ONLY barrier per iteration

        // ---- block combine: lane i <- warp i entry; same dual-redux ----
        uint2 e = sm_warp[t & 1][lane];              // 1 LDS.64, conflict-free
        unsigned gv  = __reduce_max_sync(0xFFFFFFFFu, e.x);
        const int ind = (int)__reduce_min_sync(0xFFFFFFFFu,
                            (e.x == gv) ? e.y : 0x7FFFFFFFu);
        // empty open: all keys 0 -> gv=0, min bestj over warp bases = 0,
        // matching reference argmax-of-zeros fallback.

        // ---- fetch selected row (L2-warm; evict L1 — rows never reused) ----
        const float g_ind = sm_g[ind];    // ind is never relaxed this iteration
        float4 wv = __ldcg(reinterpret_cast<const float4*>(wadj + (size_t)ind * N) + tid);
        float w4a[VPT] = {wv.x, wv.y, wv.z, wv.w};

        t_final = t;
        if (ind == goal) done = true;

        // ---- close ind (open2/hist2) ----
        if ((unsigned)(ind - j0) < VPT) {
            int k = ind - j0;
            openm &= ~(1u << k);
            histm |=  (1u << k);
            val[k] = 0u;
        }
        // ---- relax: idx == neighbor == (w!=0) & free ----
        const unsigned freem = ~(openm | histm);
        #pragma unroll
        for (int k = 0; k < VPT; k++) {
            float w = w4a[k];
            if (w != 0.0f && ((freem >> k) & 1u)) {
                int j = j0 + k;
                float gn = g_ind + w;                // g2 = g[ind] + wadj[ind,j]
                sm_g[j]   = gn;
                sm_par[j] = (unsigned short)ind;
                val[k] = __float_as_uint(expf(-(0.5f * gn + 0.5f * h4[k]) * inv_sqrt_n));
                openm |= 1u << k;                    // open3
            }
        }

        if (done) break;   // uniform branch; state frozen after goal found
    }

    __syncthreads();       // drain final sm_par writes before readout/backtrack

    // ---- outputs: [0,N) hist, [N,2N) path_maps ----
    #pragma unroll
    for (int k = 0; k < VPT; k++) {
        int j = j0 + k;
        out[j]     = ((histm >> k) & 1u) ? 1.0f : 0.0f;
        out[N + j] = 0.0f;
    }
    __syncthreads();

    if (tid == 0) {
        out[N + goal] = 1.0f;                        // path0 = goal one-hot
        int loc = sm_par[goal];
        for (int i = 0; i < t_final; i++) {
            out[N + loc] = 1.0f;
            loc = sm_par[loc];
        }
    }
}

extern "C" void kernel_launch(void* const* d_in, const int* in_sizes, int n_in,
                              void* d_out, int out_size)
{
    const int*   start = (const int*)  d_in[0];
    const int*   goal  = (const int*)  d_in[1];
    const float* h     = (const float*)d_in[2];
    // d_in[3] = nodes (unused), d_in[4] = adj (redundant with wadj != 0)
    const float* wadj  = (const float*)d_in[5];
    float* out = (float*)d_out;
    int N = in_sizes[2];                             // 4096

    astar_persistent_kernel<<<1, TPB>>>(start, goal, h, wadj, out, N);
}